// round 15
// baseline (speedup 1.0000x reference)
#include <cuda_runtime.h>
#include <cstdint>
#include <cstddef>

// ---------------------------------------------------------------------------
// SNN with cochlea front-end.  B=64, T=500, IN=256, HID=512, OUT=35.
//
// R15 = R12 pipeline (best, 474us) with ONE change in snn_main:
// 3 barriers/step -> 1 via speculation + register rollback.
//   - LIF1 is exact (current prefetched from g_cur1).
//   - LIF2/3/4 are computed SPECULATIVELY with the rowsum fast path from
//     saved old membranes (the hidden layers saturate to all-ones, so the
//     speculation is almost always exact).
//   - Zero-ballot masks + any-zero flag bytes are published, then ONE
//     __syncthreads.  Flags clear (common) => store results and continue.
//   - Flags set (rare, CTA-uniform) => recompute from the first dirty layer
//     using the validated ascending-k correct_hid mask walk (identical
//     __fadd_rn order to R12's zlist walk), rebuilding downstream masks and
//     flags with __syncthreads_count.
//   - Mask/flag buffers parity-double-buffered (2-step reuse distance).
// prep_quant / cochlea_rs / cur1_k are R12 verbatim (bit-exact).
// ---------------------------------------------------------------------------

namespace {
constexpr int T_STEPS = 500;
constexpr int BATCH   = 64;
constexpr int N_IN    = 256;
constexpr int N_HID   = 512;
constexpr int N_OUT   = 35;
constexpr int BT      = BATCH * T_STEPS;
constexpr int CH2     = 50;                      // t-chunk per cur1_k CTA
constexpr float SCALEF = (float)((1.0 - 0.001) / 31.0);
constexpr size_t SPK_HID = (size_t)T_STEPS * BATCH * N_HID;
constexpr size_t SPK_OUT = (size_t)T_STEPS * BATCH * N_OUT;
constexpr int WSTR = 132;                        // padded row stride (u32)
constexpr unsigned ZOFF = 256u * WSTR;           // sentinel zero-row offset
constexpr int SW_BYTES = 257 * WSTR * 4;         // 135,696 B dynamic smem
}  // namespace

// Static device scratch (no runtime allocation).
__device__ unsigned char g_w1q[N_IN * N_HID];
__device__ float g_q2T[N_HID * N_HID];
__device__ float g_q3T[N_HID * N_HID];
__device__ float g_q4T[N_HID * N_OUT];
__device__ float g_rs2[N_HID];
__device__ float g_rs3[N_HID];
__device__ float g_rs4[N_OUT];
__device__ unsigned g_chmask[BT * 8];            // cochlea spike masks
__device__ float g_cur1[(size_t)BT * N_HID];     // 65.5 MB layer-1 currents

// Exact replication of reference fake_quant (fp32, round-half-even, no FMA).
__device__ __forceinline__ float quantw(float w) {
    float wc = fminf(fmaxf(w, 0.001f), 1.0f);
    float l  = rintf((wc - 0.001f) / SCALEF);
    return __fadd_rn(__fmul_rn(l, SCALEF), 0.001f);
}

// ---------------------------------------------------------------------------
__global__ void prep_quant(const float* __restrict__ W1, const float* __restrict__ W2,
                           const float* __restrict__ W3, const float* __restrict__ W4) {
    int idx = blockIdx.x * blockDim.x + threadIdx.x;
    if (idx < N_HID * N_IN) {
        int n = idx / N_IN, k = idx % N_IN;
        float wc = fminf(fmaxf(W1[idx], 0.001f), 1.0f);
        float l  = rintf((wc - 0.001f) / SCALEF);
        g_w1q[k * N_HID + n] = (unsigned char)(int)l;
    }
    if (idx < N_HID * N_HID) {
        int n = idx / N_HID, k = idx % N_HID;
        g_q2T[k * N_HID + n] = quantw(W2[idx]);
        g_q3T[k * N_HID + n] = quantw(W3[idx]);
    }
    if (idx < N_OUT * N_HID) {
        int o = idx / N_HID, k = idx % N_HID;
        g_q4T[k * N_OUT + o] = quantw(W4[idx]);
    }
}

// Cochlea (all blocks) + rowsums (blocks 0-1).
__global__ void __launch_bounds__(256, 1) cochlea_rs(
    const float* __restrict__ x, const float* __restrict__ Wch,
    const float* __restrict__ cb)
{
    __shared__ float xs[T_STEPS];
    const int b = blockIdx.x, k = threadIdx.x;
    const int lane = k & 31, warp = k >> 5;
    for (int i = k; i < T_STEPS; i += 256) xs[i] = x[(size_t)b * T_STEPS + i];
    const float wch = Wch[k];
    const float bch = fminf(fmaxf(cb[k], 0.f), 1.f);
    float chm = 0.f;
    __syncthreads();
    for (int t = 0; t < T_STEPS; ++t) {
        float cur = __fmul_rn(xs[t], wch);
        float rst = (chm > 1.f) ? 1.f : 0.f;
        chm = __fadd_rn(__fadd_rn(__fmul_rn(bch, chm), cur), -rst);
        unsigned bal = __ballot_sync(0xffffffffu, chm > 1.f);
        if (lane == 0) g_chmask[((size_t)b * T_STEPS + t) * 8 + warp] = bal;
    }
    if (b < 2) {
        const int n = b * 256 + k;
        float s2 = 0.f, s3 = 0.f;
        for (int kk = 0; kk < N_HID; ++kk) {
            s2 = __fadd_rn(s2, g_q2T[kk * N_HID + n]);
            s3 = __fadd_rn(s3, g_q3T[kk * N_HID + n]);
        }
        g_rs2[n] = s2;
        g_rs3[n] = s3;
        if (n < N_OUT) {
            float s4 = 0.f;
            for (int kk = 0; kk < N_HID; ++kk)
                s4 = __fadd_rn(s4, g_q4T[kk * N_OUT + n]);
            g_rs4[n] = s4;
        }
    }
}

// No-op kernel: keeps snn_main at launch index 3 (mod 5) for ncu capture.
__global__ void pad_b() {}

// ---------------------------------------------------------------------------
// cur1_k: R12 verbatim (bit-exact layer-1 currents, time-parallel).
// ---------------------------------------------------------------------------
__global__ void __launch_bounds__(512, 1) cur1_k() {
    const int b    = blockIdx.x;
    const int t0   = blockIdx.y * CH2;
    const int tid  = threadIdx.x;
    const int lane = tid & 31;
    const int warp = tid >> 5;
    const unsigned ltm = (1u << lane) - 1u;

    extern __shared__ unsigned sw32[];
    __shared__ unsigned s_cm[CH2 * 8];
    __shared__ int      s_ccv[CH2];
    __shared__ __align__(16) unsigned s_list[2][264];

    for (int r = warp; r < 256; r += 16) {
        uint4 v = ((const uint4*)(g_w1q + r * N_HID))[lane];
        ((uint4*)(sw32 + r * WSTR))[lane] = v;
    }
    for (int r = tid; r < 256; r += 512) {
        unsigned* p = sw32 + r * WSTR + 128;
        p[0] = 0u; p[1] = 0u; p[2] = 0u; p[3] = 0u;
    }
    if (tid < WSTR) sw32[256 * WSTR + tid] = 0u;

    for (int i = tid; i < (CH2 * 8) / 4; i += 512)
        ((uint4*)s_cm)[i] =
            ((const uint4*)(g_chmask + ((size_t)b * T_STEPS + t0) * 8))[i];
    __syncthreads();
    if (tid < CH2) {
        uint4 a = ((const uint4*)s_cm)[2 * tid];
        uint4 c = ((const uint4*)s_cm)[2 * tid + 1];
        s_ccv[tid] = ((__popc(a.x) + __popc(a.y)) + (__popc(a.z) + __popc(a.w))) +
                     ((__popc(c.x) + __popc(c.y)) + (__popc(c.z) + __popc(c.w)));
    }
    __syncthreads();

    const int sl = lane & 3;
    const int wq = warp * 8 + (lane >> 2);
    float* outp = g_cur1 + ((size_t)b * T_STEPS + t0) * N_HID + tid;

    for (int tt = 0; tt < CH2; ++tt) {
        const int buf = tt & 1;
        const uint4 mA = ((const uint4*)s_cm)[2 * tt];
        const uint4 mB = ((const uint4*)s_cm)[2 * tt + 1];
        const int cc  = s_ccv[tt];
        const int ccq = ((cc + 31) >> 5) << 3;

        if (tid < N_IN) {
            const unsigned bal =
                (warp == 0) ? mA.x : (warp == 1) ? mA.y :
                (warp == 2) ? mA.z : (warp == 3) ? mA.w :
                (warp == 4) ? mB.x : (warp == 5) ? mB.y :
                (warp == 6) ? mB.z : mB.w;
            if ((bal >> lane) & 1u) {
                int off = __popc(bal & ltm);
                if (warp > 0) off += __popc(mA.x);
                if (warp > 1) off += __popc(mA.y);
                if (warp > 2) off += __popc(mA.z);
                if (warp > 3) off += __popc(mA.w);
                if (warp > 4) off += __popc(mB.x);
                if (warp > 5) off += __popc(mB.y);
                if (warp > 6) off += __popc(mB.z);
                s_list[buf][off] = (unsigned)tid * WSTR;
            }
        }
        if (tid < 4 * ccq - cc) s_list[buf][cc + tid] = ZOFF;
        __syncthreads();

        unsigned a02 = 0u, a13 = 0u;
        const int j0 = sl * ccq;
        #pragma unroll 1
        for (int j = j0; j < j0 + ccq; j += 8) {
            const uint4 i0 = *(const uint4*)&s_list[buf][j];
            const uint4 i1 = *(const uint4*)&s_list[buf][j + 4];
            const unsigned va = (sw32[i0.x + wq] + sw32[i0.y + wq]) +
                                (sw32[i0.z + wq] + sw32[i0.w + wq]);
            const unsigned vb = (sw32[i1.x + wq] + sw32[i1.y + wq]) +
                                (sw32[i1.z + wq] + sw32[i1.w + wq]);
            a02 += (va & 0x00FF00FFu) + (vb & 0x00FF00FFu);
            a13 += ((va >> 8) & 0x00FF00FFu) + ((vb >> 8) & 0x00FF00FFu);
        }
        a02 += __shfl_xor_sync(0xffffffffu, a02, 1);
        a13 += __shfl_xor_sync(0xffffffffu, a13, 1);
        a02 += __shfl_xor_sync(0xffffffffu, a02, 2);
        a13 += __shfl_xor_sync(0xffffffffu, a13, 2);
        const unsigned selv = (lane & 1) ? a13 : a02;
        const int lvl = (lane & 2) ? (int)(selv >> 16) : (int)(selv & 0xFFFFu);
        outp[(size_t)tt * N_HID] =
            __fadd_rn(__fmul_rn(0.001f, (float)cc), __fmul_rn(SCALEF, (float)lvl));
    }
}

// ---------------------------------------------------------------------------
// Rare-path corrections: rowsum + masked complement over ZERO-spike masks,
// ascending w then ascending bit => ascending k (identical __fadd_rn order
// to R12's zlist walk).  tot==512 => exact 0.
__device__ __forceinline__ float correct_hid(const unsigned* zm, float rs,
                                             const float* __restrict__ qT, int col) {
    float acc = rs; int tot = 0;
    #pragma unroll 1
    for (int w = 0; w < 16; ++w) {
        unsigned m = zm[w];
        tot += __popc(m);
        while (m) {
            int bb = __ffs(m) - 1; m &= m - 1;
            acc = __fadd_rn(acc, -__ldg(qT + (size_t)(w * 32 + bb) * N_HID + col));
        }
    }
    return (tot == N_HID) ? 0.f : acc;
}

__device__ __forceinline__ float correct_out(const unsigned* zm, float rs,
                                             const float* __restrict__ qT, int col) {
    float acc = rs; int tot = 0;
    #pragma unroll 1
    for (int w = 0; w < 16; ++w) {
        unsigned m = zm[w];
        tot += __popc(m);
        while (m) {
            int bb = __ffs(m) - 1; m &= m - 1;
            acc = __fadd_rn(acc, -__ldg(qT + (size_t)(w * 32 + bb) * N_OUT + col));
        }
    }
    return (tot == N_HID) ? 0.f : acc;
}

// ---------------------------------------------------------------------------
// Main recurrence: one CTA per batch element, 512 threads, ONE barrier/step.
// ---------------------------------------------------------------------------
__global__ void __launch_bounds__(512, 1) snn_main(
    const float* __restrict__ pb1, const float* __restrict__ pb2,
    const float* __restrict__ pb3, const float* __restrict__ pb4,
    float* __restrict__ out)
{
    const int b    = blockIdx.x;
    const int tid  = threadIdx.x;
    const int lane = tid & 31;
    const int warp = tid >> 5;

    __shared__ unsigned s_zm[2][3][16];   // [parity][layer][warp] zero masks
    __shared__ int      s_fl[2][3];       // [parity][layer] any-zero flags

    if (tid < 6) ((int*)s_fl)[tid] = 0;

    const float beta1 = fminf(fmaxf(pb1[0], 0.f), 1.f);
    const float beta2 = fminf(fmaxf(pb2[0], 0.f), 1.f);
    const float beta3 = fminf(fmaxf(pb3[0], 0.f), 1.f);
    const float beta4 = fminf(fmaxf(pb4[0], 0.f), 1.f);

    const float rs2 = g_rs2[tid];
    const float rs3 = g_rs3[tid];
    const float rs4 = (tid < N_OUT) ? g_rs4[tid] : 0.f;

    float m1 = 0.f, m2 = 0.f, m3 = 0.f, m4 = 0.f;

    const float* curb = g_cur1 + (size_t)b * T_STEPS * N_HID + tid;
    float pf[4];
    #pragma unroll
    for (int i = 0; i < 4; ++i) pf[i] = __ldg(curb + (size_t)i * N_HID);

    float* o_s1 = out + (size_t)b * N_HID + tid;
    float* o_s2 = o_s1 + SPK_HID;
    float* o_s3 = o_s2 + SPK_HID;
    float* o_s4 = out + 3 * SPK_HID + (size_t)b * N_OUT + tid;
    float* o_m4 = o_s4 + SPK_OUT;

    __syncthreads();   // flags cleared

    for (int t = 0; t < T_STEPS; ++t) {
        const int p = t & 1;
        const float cur1 = pf[t & 3];
        if (t + 4 < T_STEPS) pf[t & 3] = __ldg(curb + (size_t)(t + 4) * N_HID);

        // ---- layer 1 (exact) ----------------------------------------------
        float r = (m1 > 1.f) ? 1.f : 0.f;
        m1 = __fadd_rn(__fadd_rn(__fmul_rn(beta1, m1), cur1), -r);
        bool s1 = (m1 > 1.f);
        o_s1[(size_t)t * (BATCH * N_HID)] = s1 ? 1.f : 0.f;
        unsigned z1 = __ballot_sync(0xffffffffu, !s1);
        if (lane == 0) s_zm[p][0][warp] = z1;
        if (!s1) s_fl[p][0] = 1;

        // ---- save state; speculative layers 2/3/4 (rowsum fast path) ------
        const float m2o = m2, m3o = m3, m4o = m4;

        r = (m2 > 1.f) ? 1.f : 0.f;
        m2 = __fadd_rn(__fadd_rn(__fmul_rn(beta2, m2), rs2), -r);
        bool s2 = (m2 > 1.f);
        unsigned z2 = __ballot_sync(0xffffffffu, !s2);
        if (lane == 0) s_zm[p][1][warp] = z2;
        if (!s2) s_fl[p][1] = 1;

        r = (m3 > 1.f) ? 1.f : 0.f;
        m3 = __fadd_rn(__fadd_rn(__fmul_rn(beta3, m3), rs3), -r);
        bool s3 = (m3 > 1.f);
        unsigned z3 = __ballot_sync(0xffffffffu, !s3);
        if (lane == 0) s_zm[p][2][warp] = z3;
        if (!s3) s_fl[p][2] = 1;

        if (tid < N_OUT) {
            r = (m4 > 1.f) ? 1.f : 0.f;
            m4 = __fadd_rn(__fadd_rn(__fmul_rn(beta4, m4), rs4), -r);
        }

        // Clear NEXT parity's flags (writers of p^1 run after this barrier,
        // readers of p^1 after the next one => ordered both ways).
        if (tid >= 508 && tid < 511) s_fl[p ^ 1][tid - 508] = 0;

        __syncthreads();   // THE barrier

        int f1 = s_fl[p][0], f2 = s_fl[p][1], f3 = s_fl[p][2];

        if ((f1 | f2 | f3) != 0) {          // rare, CTA-uniform
            if (f1) {
                // layer 2 rollback: exact correction from true s1 masks
                const float c2 = correct_hid(s_zm[p][0], rs2, g_q2T, tid);
                r = (m2o > 1.f) ? 1.f : 0.f;
                m2 = __fadd_rn(__fadd_rn(__fmul_rn(beta2, m2o), c2), -r);
                s2 = (m2 > 1.f);
                unsigned nz2 = __ballot_sync(0xffffffffu, !s2);
                if (lane == 0) s_zm[p][1][warp] = nz2;
                f2 = __syncthreads_count(!s2);   // rebuild true flag + sync masks
            }
            // If f2 (true) == 0, the speculative layer-3 (rs3 from m3o) is
            // exact even when f1 was set: m3 depends only on m3o and cur3.
            if (f2) {
                const float c3 = correct_hid(s_zm[p][1], rs3, g_q3T, tid);
                r = (m3o > 1.f) ? 1.f : 0.f;
                m3 = __fadd_rn(__fadd_rn(__fmul_rn(beta3, m3o), c3), -r);
                s3 = (m3 > 1.f);
                unsigned nz3 = __ballot_sync(0xffffffffu, !s3);
                if (lane == 0) s_zm[p][2][warp] = nz3;
                f3 = __syncthreads_count(!s3);
            }
            if (f3) {
                if (tid < N_OUT) {
                    const float c4 = correct_out(s_zm[p][2], rs4, g_q4T, tid);
                    r = (m4o > 1.f) ? 1.f : 0.f;
                    m4 = __fadd_rn(__fadd_rn(__fmul_rn(beta4, m4o), c4), -r);
                }
            }
        }

        // ---- verified stores ------------------------------------------------
        const size_t tstr = (size_t)t * (BATCH * N_HID);
        o_s2[tstr] = s2 ? 1.f : 0.f;
        o_s3[tstr] = s3 ? 1.f : 0.f;
        if (tid < N_OUT) {
            o_s4[(size_t)t * (BATCH * N_OUT)] = (m4 > 1.f) ? 1.f : 0.f;
            o_m4[(size_t)t * (BATCH * N_OUT)] = m4;
        }
        // Rare-path zm[p] reads finish before the next step's barrier; zm[p]
        // is rewritten only at t+2 (after that barrier) => safe.
    }
}

// ---------------------------------------------------------------------------
// Launcher.  Inputs: x, Wch, W1, W2, W3, W4, cochlea_betas, beta1..beta4.
// Output: concat(spk1, spk2, spk3, spk4, mem4), each [T, B, F], float32.
// 5 launches per replay, snn_main at index 3 => ncu capture hits it.
// ---------------------------------------------------------------------------
extern "C" void kernel_launch(void* const* d_in, const int* in_sizes, int n_in,
                              void* d_out, int out_size) {
    const float* x   = (const float*)d_in[0];
    const float* Wch = (const float*)d_in[1];
    const float* W1  = (const float*)d_in[2];
    const float* W2  = (const float*)d_in[3];
    const float* W3  = (const float*)d_in[4];
    const float* W4  = (const float*)d_in[5];
    const float* cb  = (const float*)d_in[6];
    const float* b1  = (const float*)d_in[7];
    const float* b2  = (const float*)d_in[8];
    const float* b3  = (const float*)d_in[9];
    const float* b4  = (const float*)d_in[10];
    float* out = (float*)d_out;

    cudaFuncSetAttribute(cur1_k, cudaFuncAttributeMaxDynamicSharedMemorySize,
                         SW_BYTES);

    prep_quant<<<1024, 256>>>(W1, W2, W3, W4);            // launch 0
    cochlea_rs<<<BATCH, 256>>>(x, Wch, cb);               // launch 1
    cur1_k<<<dim3(BATCH, T_STEPS / CH2), 512, SW_BYTES>>>();  // launch 2
    snn_main<<<BATCH, 512>>>(b1, b2, b3, b4, out);        // launch 3
    pad_b<<<1, 32>>>();                                   // launch 4
}

// round 16
// speedup vs baseline: 2.8526x; 2.8526x over previous
#include <cuda_runtime.h>
#include <cstdint>
#include <cstddef>

// ---------------------------------------------------------------------------
// SNN with cochlea front-end.  B=64, T=500, IN=256, HID=512, OUT=35.
//
// R16 = R12 pipeline with snn_main's 3 barriers/step -> 1 via speculation +
// register rollback, fixing R15's two defects:
//   1. #pragma unroll 4 restored -> pf[] prefetch stays in REGISTERS
//      (R15 dropped it; pf went to local memory on the serial path).
//   2. rollback uses (any-zero, any-one) flag pairs: all-zero layers get
//      cur = 0 with ZERO loads (R12's zc==512 fast path); mixed layers use
//      the ascending-k correct_hid walk (bit-identical order to R12's
//      zlist).  R15 walked all 512 zero bits on silent steps.
// prep_quant / cochlea_rs / cur1_k are R12 verbatim (bit-exact).
// ---------------------------------------------------------------------------

namespace {
constexpr int T_STEPS = 500;
constexpr int BATCH   = 64;
constexpr int N_IN    = 256;
constexpr int N_HID   = 512;
constexpr int N_OUT   = 35;
constexpr int BT      = BATCH * T_STEPS;
constexpr int CH2     = 50;                      // t-chunk per cur1_k CTA
constexpr float SCALEF = (float)((1.0 - 0.001) / 31.0);
constexpr size_t SPK_HID = (size_t)T_STEPS * BATCH * N_HID;
constexpr size_t SPK_OUT = (size_t)T_STEPS * BATCH * N_OUT;
constexpr int WSTR = 132;                        // padded row stride (u32)
constexpr unsigned ZOFF = 256u * WSTR;           // sentinel zero-row offset
constexpr int SW_BYTES = 257 * WSTR * 4;         // 135,696 B dynamic smem
}  // namespace

// Static device scratch (no runtime allocation).
__device__ unsigned char g_w1q[N_IN * N_HID];
__device__ float g_q2T[N_HID * N_HID];
__device__ float g_q3T[N_HID * N_HID];
__device__ float g_q4T[N_HID * N_OUT];
__device__ float g_rs2[N_HID];
__device__ float g_rs3[N_HID];
__device__ float g_rs4[N_OUT];
__device__ unsigned g_chmask[BT * 8];            // cochlea spike masks
__device__ float g_cur1[(size_t)BT * N_HID];     // 65.5 MB layer-1 currents

// Exact replication of reference fake_quant (fp32, round-half-even, no FMA).
__device__ __forceinline__ float quantw(float w) {
    float wc = fminf(fmaxf(w, 0.001f), 1.0f);
    float l  = rintf((wc - 0.001f) / SCALEF);
    return __fadd_rn(__fmul_rn(l, SCALEF), 0.001f);
}

// ---------------------------------------------------------------------------
__global__ void prep_quant(const float* __restrict__ W1, const float* __restrict__ W2,
                           const float* __restrict__ W3, const float* __restrict__ W4) {
    int idx = blockIdx.x * blockDim.x + threadIdx.x;
    if (idx < N_HID * N_IN) {
        int n = idx / N_IN, k = idx % N_IN;
        float wc = fminf(fmaxf(W1[idx], 0.001f), 1.0f);
        float l  = rintf((wc - 0.001f) / SCALEF);
        g_w1q[k * N_HID + n] = (unsigned char)(int)l;
    }
    if (idx < N_HID * N_HID) {
        int n = idx / N_HID, k = idx % N_HID;
        g_q2T[k * N_HID + n] = quantw(W2[idx]);
        g_q3T[k * N_HID + n] = quantw(W3[idx]);
    }
    if (idx < N_OUT * N_HID) {
        int o = idx / N_HID, k = idx % N_HID;
        g_q4T[k * N_OUT + o] = quantw(W4[idx]);
    }
}

// Cochlea (all blocks) + rowsums (blocks 0-1).
__global__ void __launch_bounds__(256, 1) cochlea_rs(
    const float* __restrict__ x, const float* __restrict__ Wch,
    const float* __restrict__ cb)
{
    __shared__ float xs[T_STEPS];
    const int b = blockIdx.x, k = threadIdx.x;
    const int lane = k & 31, warp = k >> 5;
    for (int i = k; i < T_STEPS; i += 256) xs[i] = x[(size_t)b * T_STEPS + i];
    const float wch = Wch[k];
    const float bch = fminf(fmaxf(cb[k], 0.f), 1.f);
    float chm = 0.f;
    __syncthreads();
    for (int t = 0; t < T_STEPS; ++t) {
        float cur = __fmul_rn(xs[t], wch);
        float rst = (chm > 1.f) ? 1.f : 0.f;
        chm = __fadd_rn(__fadd_rn(__fmul_rn(bch, chm), cur), -rst);
        unsigned bal = __ballot_sync(0xffffffffu, chm > 1.f);
        if (lane == 0) g_chmask[((size_t)b * T_STEPS + t) * 8 + warp] = bal;
    }
    if (b < 2) {
        const int n = b * 256 + k;
        float s2 = 0.f, s3 = 0.f;
        for (int kk = 0; kk < N_HID; ++kk) {
            s2 = __fadd_rn(s2, g_q2T[kk * N_HID + n]);
            s3 = __fadd_rn(s3, g_q3T[kk * N_HID + n]);
        }
        g_rs2[n] = s2;
        g_rs3[n] = s3;
        if (n < N_OUT) {
            float s4 = 0.f;
            for (int kk = 0; kk < N_HID; ++kk)
                s4 = __fadd_rn(s4, g_q4T[kk * N_OUT + n]);
            g_rs4[n] = s4;
        }
    }
}

// No-op kernel: keeps snn_main at launch index 3 (mod 5) for ncu capture.
__global__ void pad_b() {}

// ---------------------------------------------------------------------------
// cur1_k: R12 verbatim (bit-exact layer-1 currents, time-parallel).
// ---------------------------------------------------------------------------
__global__ void __launch_bounds__(512, 1) cur1_k() {
    const int b    = blockIdx.x;
    const int t0   = blockIdx.y * CH2;
    const int tid  = threadIdx.x;
    const int lane = tid & 31;
    const int warp = tid >> 5;
    const unsigned ltm = (1u << lane) - 1u;

    extern __shared__ unsigned sw32[];
    __shared__ unsigned s_cm[CH2 * 8];
    __shared__ int      s_ccv[CH2];
    __shared__ __align__(16) unsigned s_list[2][264];

    for (int r = warp; r < 256; r += 16) {
        uint4 v = ((const uint4*)(g_w1q + r * N_HID))[lane];
        ((uint4*)(sw32 + r * WSTR))[lane] = v;
    }
    for (int r = tid; r < 256; r += 512) {
        unsigned* p = sw32 + r * WSTR + 128;
        p[0] = 0u; p[1] = 0u; p[2] = 0u; p[3] = 0u;
    }
    if (tid < WSTR) sw32[256 * WSTR + tid] = 0u;

    for (int i = tid; i < (CH2 * 8) / 4; i += 512)
        ((uint4*)s_cm)[i] =
            ((const uint4*)(g_chmask + ((size_t)b * T_STEPS + t0) * 8))[i];
    __syncthreads();
    if (tid < CH2) {
        uint4 a = ((const uint4*)s_cm)[2 * tid];
        uint4 c = ((const uint4*)s_cm)[2 * tid + 1];
        s_ccv[tid] = ((__popc(a.x) + __popc(a.y)) + (__popc(a.z) + __popc(a.w))) +
                     ((__popc(c.x) + __popc(c.y)) + (__popc(c.z) + __popc(c.w)));
    }
    __syncthreads();

    const int sl = lane & 3;
    const int wq = warp * 8 + (lane >> 2);
    float* outp = g_cur1 + ((size_t)b * T_STEPS + t0) * N_HID + tid;

    for (int tt = 0; tt < CH2; ++tt) {
        const int buf = tt & 1;
        const uint4 mA = ((const uint4*)s_cm)[2 * tt];
        const uint4 mB = ((const uint4*)s_cm)[2 * tt + 1];
        const int cc  = s_ccv[tt];
        const int ccq = ((cc + 31) >> 5) << 3;

        if (tid < N_IN) {
            const unsigned bal =
                (warp == 0) ? mA.x : (warp == 1) ? mA.y :
                (warp == 2) ? mA.z : (warp == 3) ? mA.w :
                (warp == 4) ? mB.x : (warp == 5) ? mB.y :
                (warp == 6) ? mB.z : mB.w;
            if ((bal >> lane) & 1u) {
                int off = __popc(bal & ltm);
                if (warp > 0) off += __popc(mA.x);
                if (warp > 1) off += __popc(mA.y);
                if (warp > 2) off += __popc(mA.z);
                if (warp > 3) off += __popc(mA.w);
                if (warp > 4) off += __popc(mB.x);
                if (warp > 5) off += __popc(mB.y);
                if (warp > 6) off += __popc(mB.z);
                s_list[buf][off] = (unsigned)tid * WSTR;
            }
        }
        if (tid < 4 * ccq - cc) s_list[buf][cc + tid] = ZOFF;
        __syncthreads();

        unsigned a02 = 0u, a13 = 0u;
        const int j0 = sl * ccq;
        #pragma unroll 1
        for (int j = j0; j < j0 + ccq; j += 8) {
            const uint4 i0 = *(const uint4*)&s_list[buf][j];
            const uint4 i1 = *(const uint4*)&s_list[buf][j + 4];
            const unsigned va = (sw32[i0.x + wq] + sw32[i0.y + wq]) +
                                (sw32[i0.z + wq] + sw32[i0.w + wq]);
            const unsigned vb = (sw32[i1.x + wq] + sw32[i1.y + wq]) +
                                (sw32[i1.z + wq] + sw32[i1.w + wq]);
            a02 += (va & 0x00FF00FFu) + (vb & 0x00FF00FFu);
            a13 += ((va >> 8) & 0x00FF00FFu) + ((vb >> 8) & 0x00FF00FFu);
        }
        a02 += __shfl_xor_sync(0xffffffffu, a02, 1);
        a13 += __shfl_xor_sync(0xffffffffu, a13, 1);
        a02 += __shfl_xor_sync(0xffffffffu, a02, 2);
        a13 += __shfl_xor_sync(0xffffffffu, a13, 2);
        const unsigned selv = (lane & 1) ? a13 : a02;
        const int lvl = (lane & 2) ? (int)(selv >> 16) : (int)(selv & 0xFFFFu);
        outp[(size_t)tt * N_HID] =
            __fadd_rn(__fmul_rn(0.001f, (float)cc), __fmul_rn(SCALEF, (float)lvl));
    }
}

// ---------------------------------------------------------------------------
// Mixed-state corrections: rowsum + masked complement over ZERO-spike masks,
// ascending w then ascending bit => ascending k (identical __fadd_rn order
// to R12's zlist walk).  Callers guarantee the mask is neither all-zero nor
// all-one-bits (mixed state), so no tot guard is needed.
__device__ __forceinline__ float correct_hid(const unsigned* zm, float rs,
                                             const float* __restrict__ qT, int col) {
    float acc = rs;
    #pragma unroll 1
    for (int w = 0; w < 16; ++w) {
        unsigned m = zm[w];
        while (m) {
            int bb = __ffs(m) - 1; m &= m - 1;
            acc = __fadd_rn(acc, -__ldg(qT + (size_t)(w * 32 + bb) * N_HID + col));
        }
    }
    return acc;
}

__device__ __forceinline__ float correct_out(const unsigned* zm, float rs,
                                             const float* __restrict__ qT, int col) {
    float acc = rs;
    #pragma unroll 1
    for (int w = 0; w < 16; ++w) {
        unsigned m = zm[w];
        while (m) {
            int bb = __ffs(m) - 1; m &= m - 1;
            acc = __fadd_rn(acc, -__ldg(qT + (size_t)(w * 32 + bb) * N_OUT + col));
        }
    }
    return acc;
}

// ---------------------------------------------------------------------------
// Main recurrence: one CTA per batch element, 512 threads, ONE barrier per
// step on the (dominant) fully-saturated path.
// Flags per layer: f = any-zero, g = any-one.  States: 0 = all-ones,
// 1 = mixed, 2 = all-zero (cur = 0 with zero loads).
// ---------------------------------------------------------------------------
__global__ void __launch_bounds__(512, 1) snn_main(
    const float* __restrict__ pb1, const float* __restrict__ pb2,
    const float* __restrict__ pb3, const float* __restrict__ pb4,
    float* __restrict__ out)
{
    const int b    = blockIdx.x;
    const int tid  = threadIdx.x;
    const int lane = tid & 31;
    const int warp = tid >> 5;

    __shared__ unsigned s_zm[2][3][16];   // [parity][layer][warp] zero masks
    __shared__ int      s_fl[2][6];       // [parity][f1,g1,f2,g2,f3,g3]

    if (tid < 12) ((int*)s_fl)[tid] = 0;

    const float beta1 = fminf(fmaxf(pb1[0], 0.f), 1.f);
    const float beta2 = fminf(fmaxf(pb2[0], 0.f), 1.f);
    const float beta3 = fminf(fmaxf(pb3[0], 0.f), 1.f);
    const float beta4 = fminf(fmaxf(pb4[0], 0.f), 1.f);

    const float rs2 = g_rs2[tid];
    const float rs3 = g_rs3[tid];
    const float rs4 = (tid < N_OUT) ? g_rs4[tid] : 0.f;

    float m1 = 0.f, m2 = 0.f, m3 = 0.f, m4 = 0.f;

    const float* curb = g_cur1 + (size_t)b * T_STEPS * N_HID + tid;
    float pf[4];
    #pragma unroll
    for (int i = 0; i < 4; ++i) pf[i] = __ldg(curb + (size_t)i * N_HID);

    float* o_s1 = out + (size_t)b * N_HID + tid;
    float* o_s2 = o_s1 + SPK_HID;
    float* o_s3 = o_s2 + SPK_HID;
    float* o_s4 = out + 3 * SPK_HID + (size_t)b * N_OUT + tid;
    float* o_m4 = o_s4 + SPK_OUT;

    __syncthreads();   // flags cleared

    #pragma unroll 4
    for (int t = 0; t < T_STEPS; ++t) {
        const int p = t & 1;
        const float cur1 = pf[t & 3];
        if (t + 4 < T_STEPS) pf[t & 3] = __ldg(curb + (size_t)(t + 4) * N_HID);

        // ---- layer 1 (exact) ----------------------------------------------
        float r = (m1 > 1.f) ? 1.f : 0.f;
        m1 = __fadd_rn(__fadd_rn(__fmul_rn(beta1, m1), cur1), -r);
        bool s1 = (m1 > 1.f);
        o_s1[(size_t)t * (BATCH * N_HID)] = s1 ? 1.f : 0.f;
        const unsigned z1 = __ballot_sync(0xffffffffu, !s1);
        if (lane == 0) {
            s_zm[p][0][warp] = z1;
            if (z1) s_fl[p][0] = 1;                    // any zero
            if (z1 != 0xffffffffu) s_fl[p][1] = 1;     // any one
        }

        // ---- save state; speculative layers 2/3/4 (rowsum fast path) ------
        const float m2o = m2, m3o = m3, m4o = m4;

        r = (m2 > 1.f) ? 1.f : 0.f;
        m2 = __fadd_rn(__fadd_rn(__fmul_rn(beta2, m2), rs2), -r);
        bool s2 = (m2 > 1.f);
        const unsigned z2 = __ballot_sync(0xffffffffu, !s2);
        if (lane == 0) {
            s_zm[p][1][warp] = z2;
            if (z2) s_fl[p][2] = 1;
            if (z2 != 0xffffffffu) s_fl[p][3] = 1;
        }

        r = (m3 > 1.f) ? 1.f : 0.f;
        m3 = __fadd_rn(__fadd_rn(__fmul_rn(beta3, m3), rs3), -r);
        bool s3 = (m3 > 1.f);
        const unsigned z3 = __ballot_sync(0xffffffffu, !s3);
        if (lane == 0) {
            s_zm[p][2][warp] = z3;
            if (z3) s_fl[p][4] = 1;
            if (z3 != 0xffffffffu) s_fl[p][5] = 1;
        }

        if (tid < N_OUT) {
            r = (m4 > 1.f) ? 1.f : 0.f;
            m4 = __fadd_rn(__fadd_rn(__fmul_rn(beta4, m4), rs4), -r);
        }

        // Clear NEXT parity's flags (ordered by the barriers on both sides).
        if (tid >= 504 && tid < 510) s_fl[p ^ 1][tid - 504] = 0;

        __syncthreads();   // THE barrier

        const int f1 = s_fl[p][0], g1 = s_fl[p][1];
        const int f2 = s_fl[p][2], g2 = s_fl[p][3];
        const int f3 = s_fl[p][4], g3 = s_fl[p][5];

        if ((f1 | f2 | f3) != 0) {          // CTA-uniform rollback
            // state: 0 = all-ones, 1 = mixed, 2 = all-zero
            const int st1 = f1 ? (g1 ? 1 : 2) : 0;
            int st2;
            if (st1 != 0) {                 // spec layer-2 invalid: redo
                float c2 = 0.f;
                if (st1 == 1) c2 = correct_hid(s_zm[p][0], rs2, g_q2T, tid);
                r = (m2o > 1.f) ? 1.f : 0.f;
                m2 = __fadd_rn(__fadd_rn(__fmul_rn(beta2, m2o), c2), -r);
                s2 = (m2 > 1.f);
                const unsigned nz2 = __ballot_sync(0xffffffffu, !s2);
                if (lane == 0) s_zm[p][1][warp] = nz2;
                const int zc2 = __syncthreads_count(!s2);
                st2 = (zc2 == 0) ? 0 : ((zc2 == N_HID) ? 2 : 1);
            } else {
                st2 = f2 ? (g2 ? 1 : 2) : 0;
            }
            int st3;
            if (st2 != 0) {                 // spec layer-3 invalid: redo
                float c3 = 0.f;
                if (st2 == 1) c3 = correct_hid(s_zm[p][1], rs3, g_q3T, tid);
                r = (m3o > 1.f) ? 1.f : 0.f;
                m3 = __fadd_rn(__fadd_rn(__fmul_rn(beta3, m3o), c3), -r);
                s3 = (m3 > 1.f);
                const unsigned nz3 = __ballot_sync(0xffffffffu, !s3);
                if (lane == 0) s_zm[p][2][warp] = nz3;
                const int zc3 = __syncthreads_count(!s3);
                st3 = (zc3 == 0) ? 0 : ((zc3 == N_HID) ? 2 : 1);
            } else {
                st3 = f3 ? (g3 ? 1 : 2) : 0;
            }
            if (st3 != 0 && tid < N_OUT) {  // spec layer-4 invalid: redo
                float c4 = 0.f;
                if (st3 == 1) c4 = correct_out(s_zm[p][2], rs4, g_q4T, tid);
                r = (m4o > 1.f) ? 1.f : 0.f;
                m4 = __fadd_rn(__fadd_rn(__fmul_rn(beta4, m4o), c4), -r);
            }
        }

        // ---- verified stores ------------------------------------------------
        const size_t tstr = (size_t)t * (BATCH * N_HID);
        o_s2[tstr] = s2 ? 1.f : 0.f;
        o_s3[tstr] = s3 ? 1.f : 0.f;
        if (tid < N_OUT) {
            o_s4[(size_t)t * (BATCH * N_OUT)] = (m4 > 1.f) ? 1.f : 0.f;
            o_m4[(size_t)t * (BATCH * N_OUT)] = m4;
        }
        // zm[p] is rewritten only at t+2, after the t+1 barrier => safe.
    }
}

// ---------------------------------------------------------------------------
// Launcher.  Inputs: x, Wch, W1, W2, W3, W4, cochlea_betas, beta1..beta4.
// Output: concat(spk1, spk2, spk3, spk4, mem4), each [T, B, F], float32.
// 5 launches per replay, snn_main at index 3 => ncu capture hits it.
// ---------------------------------------------------------------------------
extern "C" void kernel_launch(void* const* d_in, const int* in_sizes, int n_in,
                              void* d_out, int out_size) {
    const float* x   = (const float*)d_in[0];
    const float* Wch = (const float*)d_in[1];
    const float* W1  = (const float*)d_in[2];
    const float* W2  = (const float*)d_in[3];
    const float* W3  = (const float*)d_in[4];
    const float* W4  = (const float*)d_in[5];
    const float* cb  = (const float*)d_in[6];
    const float* b1  = (const float*)d_in[7];
    const float* b2  = (const float*)d_in[8];
    const float* b3  = (const float*)d_in[9];
    const float* b4  = (const float*)d_in[10];
    float* out = (float*)d_out;

    cudaFuncSetAttribute(cur1_k, cudaFuncAttributeMaxDynamicSharedMemorySize,
                         SW_BYTES);

    prep_quant<<<1024, 256>>>(W1, W2, W3, W4);            // launch 0
    cochlea_rs<<<BATCH, 256>>>(x, Wch, cb);               // launch 1
    cur1_k<<<dim3(BATCH, T_STEPS / CH2), 512, SW_BYTES>>>();  // launch 2
    snn_main<<<BATCH, 512>>>(b1, b2, b3, b4, out);        // launch 3
    pad_b<<<1, 32>>>();                                   // launch 4
}

// round 17
// speedup vs baseline: 5.1498x; 1.8053x over previous
#include <cuda_runtime.h>
#include <cstdint>
#include <cstddef>

// ---------------------------------------------------------------------------
// SNN with cochlea front-end.  B=64, T=500, IN=256, HID=512, OUT=35.
//
// R17 = R12 (best, 474us) with ONE change: cur1_k split over the neuron
// dimension.  Each CTA handles 256 of the 512 neurons (64 u32 weight words,
// row stride 68 => 68.3 KB smem) with 256 threads / 8 warps; grid
// (64 batches x 10 chunks x 2 halves) = 1280 CTAs, 3 resident per SM
// (vs 1 before) => 3-way overlap of the per-step barrier + LDS-walk latency.
// The 4-slice list partition and 8-entry u8 regrouping are unchanged and all
// sums are exact integers => bit-identical currents.
// snn_main / cochlea_rs / prep_quant are byte-identical to R12.
// ---------------------------------------------------------------------------

namespace {
constexpr int T_STEPS = 500;
constexpr int BATCH   = 64;
constexpr int N_IN    = 256;
constexpr int N_HID   = 512;
constexpr int N_OUT   = 35;
constexpr int BT      = BATCH * T_STEPS;
constexpr int CH2     = 50;                      // t-chunk per cur1_k CTA
constexpr float SCALEF = (float)((1.0 - 0.001) / 31.0);
constexpr size_t SPK_HID = (size_t)T_STEPS * BATCH * N_HID;
constexpr size_t SPK_OUT = (size_t)T_STEPS * BATCH * N_OUT;
constexpr int WSTR = 68;                         // padded row stride (u32), half
constexpr unsigned ZOFF = 256u * WSTR;           // sentinel zero-row offset
constexpr int SW_BYTES = 257 * WSTR * 4;         // 69,904 B dynamic smem
}  // namespace

// Static device scratch (no runtime allocation).
__device__ unsigned char g_w1q[N_IN * N_HID];
__device__ float g_q2T[N_HID * N_HID];
__device__ float g_q3T[N_HID * N_HID];
__device__ float g_q4T[N_HID * N_OUT];
__device__ float g_rs2[N_HID];
__device__ float g_rs3[N_HID];
__device__ float g_rs4[N_OUT];
__device__ unsigned g_chmask[BT * 8];            // cochlea spike masks
__device__ float g_cur1[(size_t)BT * N_HID];     // 65.5 MB layer-1 currents

// Exact replication of reference fake_quant (fp32, round-half-even, no FMA).
__device__ __forceinline__ float quantw(float w) {
    float wc = fminf(fmaxf(w, 0.001f), 1.0f);
    float l  = rintf((wc - 0.001f) / SCALEF);
    return __fadd_rn(__fmul_rn(l, SCALEF), 0.001f);
}

// ---------------------------------------------------------------------------
__global__ void prep_quant(const float* __restrict__ W1, const float* __restrict__ W2,
                           const float* __restrict__ W3, const float* __restrict__ W4) {
    int idx = blockIdx.x * blockDim.x + threadIdx.x;
    if (idx < N_HID * N_IN) {
        int n = idx / N_IN, k = idx % N_IN;
        float wc = fminf(fmaxf(W1[idx], 0.001f), 1.0f);
        float l  = rintf((wc - 0.001f) / SCALEF);
        g_w1q[k * N_HID + n] = (unsigned char)(int)l;
    }
    if (idx < N_HID * N_HID) {
        int n = idx / N_HID, k = idx % N_HID;
        g_q2T[k * N_HID + n] = quantw(W2[idx]);
        g_q3T[k * N_HID + n] = quantw(W3[idx]);
    }
    if (idx < N_OUT * N_HID) {
        int o = idx / N_HID, k = idx % N_HID;
        g_q4T[k * N_OUT + o] = quantw(W4[idx]);
    }
}

// Cochlea (all blocks) + rowsums (blocks 0-1).
__global__ void __launch_bounds__(256, 1) cochlea_rs(
    const float* __restrict__ x, const float* __restrict__ Wch,
    const float* __restrict__ cb)
{
    __shared__ float xs[T_STEPS];
    const int b = blockIdx.x, k = threadIdx.x;
    const int lane = k & 31, warp = k >> 5;
    for (int i = k; i < T_STEPS; i += 256) xs[i] = x[(size_t)b * T_STEPS + i];
    const float wch = Wch[k];
    const float bch = fminf(fmaxf(cb[k], 0.f), 1.f);
    float chm = 0.f;
    __syncthreads();
    for (int t = 0; t < T_STEPS; ++t) {
        float cur = __fmul_rn(xs[t], wch);
        float rst = (chm > 1.f) ? 1.f : 0.f;
        chm = __fadd_rn(__fadd_rn(__fmul_rn(bch, chm), cur), -rst);
        unsigned bal = __ballot_sync(0xffffffffu, chm > 1.f);
        if (lane == 0) g_chmask[((size_t)b * T_STEPS + t) * 8 + warp] = bal;
    }
    if (b < 2) {
        const int n = b * 256 + k;
        float s2 = 0.f, s3 = 0.f;
        for (int kk = 0; kk < N_HID; ++kk) {
            s2 = __fadd_rn(s2, g_q2T[kk * N_HID + n]);
            s3 = __fadd_rn(s3, g_q3T[kk * N_HID + n]);
        }
        g_rs2[n] = s2;
        g_rs3[n] = s3;
        if (n < N_OUT) {
            float s4 = 0.f;
            for (int kk = 0; kk < N_HID; ++kk)
                s4 = __fadd_rn(s4, g_q4T[kk * N_OUT + n]);
            g_rs4[n] = s4;
        }
    }
}

// No-op kernel: keeps snn_main at launch index 3 (mod 5) for ncu capture.
__global__ void pad_b() {}

// ---------------------------------------------------------------------------
// cur1_k: R12's list-build + in-warp-sliced walk, split over neuron halves.
// Grid (64, 10, 2); block 256 threads (8 warps).  Half h covers neurons
// 256h..256h+255 = weight words 64h..64h+63 (staged at row stride 68).
// ---------------------------------------------------------------------------
__global__ void __launch_bounds__(256, 3) cur1_k() {
    const int b    = blockIdx.x;
    const int t0   = blockIdx.y * CH2;
    const int h    = blockIdx.z;
    const int tid  = threadIdx.x;
    const int lane = tid & 31;
    const int warp = tid >> 5;                   // 0..7
    const unsigned ltm = (1u << lane) - 1u;

    extern __shared__ unsigned sw32[];           // 257 x 68 u32 (row 256 = 0)
    __shared__ unsigned s_cm[CH2 * 8];
    __shared__ int      s_ccv[CH2];
    __shared__ __align__(16) unsigned s_list[2][264];

    // Stage this half's weight words: row k words [64h, 64h+64) -> k*68.
    for (int r = warp; r < 256; r += 8) {
        if (lane < 16) {
            uint4 v = ((const uint4*)(g_w1q + r * N_HID + 256 * h))[lane];
            ((uint4*)(sw32 + r * WSTR))[lane] = v;
        }
    }
    if (tid < WSTR) sw32[256 * WSTR + tid] = 0u;     // sentinel zero row

    // Stage this chunk's masks, then counts.
    for (int i = tid; i < (CH2 * 8) / 4; i += 256)
        ((uint4*)s_cm)[i] =
            ((const uint4*)(g_chmask + ((size_t)b * T_STEPS + t0) * 8))[i];
    __syncthreads();
    if (tid < CH2) {
        uint4 a = ((const uint4*)s_cm)[2 * tid];
        uint4 c = ((const uint4*)s_cm)[2 * tid + 1];
        s_ccv[tid] = ((__popc(a.x) + __popc(a.y)) + (__popc(a.z) + __popc(a.w))) +
                     ((__popc(c.x) + __popc(c.y)) + (__popc(c.z) + __popc(c.w)));
    }
    __syncthreads();

    const int sl = lane & 3;                     // 4 K-slices (as in R12)
    const int wq = tid >> 2;                     // local word 0..63
    float* outp = g_cur1 + ((size_t)b * T_STEPS + t0) * N_HID + 256 * h + tid;

    for (int tt = 0; tt < CH2; ++tt) {
        const int buf = tt & 1;
        const uint4 mA = ((const uint4*)s_cm)[2 * tt];
        const uint4 mB = ((const uint4*)s_cm)[2 * tt + 1];
        const int cc  = s_ccv[tt];
        const int ccq = ((cc + 31) >> 5) << 3;   // identical to R12

        // List build: tid in [0,256) = channel index.
        {
            const unsigned bal =
                (warp == 0) ? mA.x : (warp == 1) ? mA.y :
                (warp == 2) ? mA.z : (warp == 3) ? mA.w :
                (warp == 4) ? mB.x : (warp == 5) ? mB.y :
                (warp == 6) ? mB.z : mB.w;
            if ((bal >> lane) & 1u) {
                int off = __popc(bal & ltm);
                if (warp > 0) off += __popc(mA.x);
                if (warp > 1) off += __popc(mA.y);
                if (warp > 2) off += __popc(mA.z);
                if (warp > 3) off += __popc(mA.w);
                if (warp > 4) off += __popc(mB.x);
                if (warp > 5) off += __popc(mB.y);
                if (warp > 6) off += __popc(mB.z);
                s_list[buf][off] = (unsigned)tid * WSTR;
            }
        }
        if (tid < 4 * ccq - cc) s_list[buf][cc + tid] = ZOFF;
        __syncthreads();   // list ready (double buffer: 1 barrier/step safe)

        unsigned a02 = 0u, a13 = 0u;
        const int j0 = sl * ccq;
        #pragma unroll 1
        for (int j = j0; j < j0 + ccq; j += 8) {
            const uint4 i0 = *(const uint4*)&s_list[buf][j];
            const uint4 i1 = *(const uint4*)&s_list[buf][j + 4];
            const unsigned va = (sw32[i0.x + wq] + sw32[i0.y + wq]) +
                                (sw32[i0.z + wq] + sw32[i0.w + wq]);
            const unsigned vb = (sw32[i1.x + wq] + sw32[i1.y + wq]) +
                                (sw32[i1.z + wq] + sw32[i1.w + wq]);
            a02 += (va & 0x00FF00FFu) + (vb & 0x00FF00FFu);
            a13 += ((va >> 8) & 0x00FF00FFu) + ((vb >> 8) & 0x00FF00FFu);
        }
        // Reduce the 4 slices (u16 fields < 2^16: exact integers).
        a02 += __shfl_xor_sync(0xffffffffu, a02, 1);
        a13 += __shfl_xor_sync(0xffffffffu, a13, 1);
        a02 += __shfl_xor_sync(0xffffffffu, a02, 2);
        a13 += __shfl_xor_sync(0xffffffffu, a13, 2);
        const unsigned selv = (lane & 1) ? a13 : a02;
        const int lvl = (lane & 2) ? (int)(selv >> 16) : (int)(selv & 0xFFFFu);
        outp[(size_t)tt * N_HID] =
            __fadd_rn(__fmul_rn(0.001f, (float)cc), __fmul_rn(SCALEF, (float)lvl));
    }
}

// ---------------------------------------------------------------------------
// Main recurrence: R12 verbatim.  One CTA per batch element, 512 threads;
// cur1 arrives via a 4-deep register prefetch (unroll 4 keeps pf in regs).
// ---------------------------------------------------------------------------
__global__ void __launch_bounds__(512, 1) snn_main(
    const float* __restrict__ pb1, const float* __restrict__ pb2,
    const float* __restrict__ pb3, const float* __restrict__ pb4,
    float* __restrict__ out)
{
    const int b    = blockIdx.x;
    const int tid  = threadIdx.x;
    const int lane = tid & 31;
    const int warp = tid >> 5;
    const unsigned ltm = (1u << lane) - 1u;

    __shared__ unsigned s_zmask[16];
    __shared__ int      s_zlist[N_HID];

    const float beta1 = fminf(fmaxf(pb1[0], 0.f), 1.f);
    const float beta2 = fminf(fmaxf(pb2[0], 0.f), 1.f);
    const float beta3 = fminf(fmaxf(pb3[0], 0.f), 1.f);
    const float beta4 = fminf(fmaxf(pb4[0], 0.f), 1.f);

    const float rs2 = g_rs2[tid];
    const float rs3 = g_rs3[tid];
    const float rs4 = (tid < N_OUT) ? g_rs4[tid] : 0.f;

    float m1 = 0.f, m2 = 0.f, m3 = 0.f, m4 = 0.f;

    const float* curb = g_cur1 + (size_t)b * T_STEPS * N_HID + tid;
    float pf[4];
    #pragma unroll
    for (int i = 0; i < 4; ++i) pf[i] = __ldg(curb + (size_t)i * N_HID);

    float* o_s1 = out + (size_t)b * N_HID + tid;
    float* o_s2 = o_s1 + SPK_HID;
    float* o_s3 = o_s2 + SPK_HID;
    float* o_s4 = out + 3 * SPK_HID + (size_t)b * N_OUT + tid;
    float* o_m4 = o_s4 + SPK_OUT;

    #pragma unroll 4
    for (int t = 0; t < T_STEPS; ++t) {
        const float cur1 = pf[t & 3];
        if (t + 4 < T_STEPS) pf[t & 3] = __ldg(curb + (size_t)(t + 4) * N_HID);

        float rst1 = (m1 > 1.f) ? 1.f : 0.f;
        m1 = __fadd_rn(__fadd_rn(__fmul_rn(beta1, m1), cur1), -rst1);
        bool s1 = (m1 > 1.f);
        o_s1[(size_t)t * (BATCH * N_HID)] = s1 ? 1.f : 0.f;

        unsigned zb = __ballot_sync(0xffffffffu, !s1);
        if (lane == 0) s_zmask[warp] = zb;
        int zc = __syncthreads_count(!s1);            // barrier #1 (+count)
        if (zc > 0 && zc < N_HID) {
            if (!s1) {
                int off = __popc(zb & ltm);
                #pragma unroll
                for (int j = 0; j < 16; ++j) off += (j < warp) ? __popc(s_zmask[j]) : 0;
                s_zlist[off] = tid;
            }
            __syncthreads();
        }

        float cur2 = 0.f;
        if (zc < N_HID) {
            cur2 = rs2;
            for (int j = 0; j < zc; ++j)
                cur2 = __fadd_rn(cur2, -g_q2T[s_zlist[j] * N_HID + tid]);
        }
        float rst2 = (m2 > 1.f) ? 1.f : 0.f;
        m2 = __fadd_rn(__fadd_rn(__fmul_rn(beta2, m2), cur2), -rst2);
        bool s2 = (m2 > 1.f);
        o_s2[(size_t)t * (BATCH * N_HID)] = s2 ? 1.f : 0.f;

        zb = __ballot_sync(0xffffffffu, !s2);
        if (lane == 0) s_zmask[warp] = zb;
        zc = __syncthreads_count(!s2);                // barrier #2 (+count)
        if (zc > 0 && zc < N_HID) {
            if (!s2) {
                int off = __popc(zb & ltm);
                #pragma unroll
                for (int j = 0; j < 16; ++j) off += (j < warp) ? __popc(s_zmask[j]) : 0;
                s_zlist[off] = tid;
            }
            __syncthreads();
        }

        float cur3 = 0.f;
        if (zc < N_HID) {
            cur3 = rs3;
            for (int j = 0; j < zc; ++j)
                cur3 = __fadd_rn(cur3, -g_q3T[s_zlist[j] * N_HID + tid]);
        }
        float rst3 = (m3 > 1.f) ? 1.f : 0.f;
        m3 = __fadd_rn(__fadd_rn(__fmul_rn(beta3, m3), cur3), -rst3);
        bool s3 = (m3 > 1.f);
        o_s3[(size_t)t * (BATCH * N_HID)] = s3 ? 1.f : 0.f;

        zb = __ballot_sync(0xffffffffu, !s3);
        if (lane == 0) s_zmask[warp] = zb;
        zc = __syncthreads_count(!s3);                // barrier #3 (+count)
        if (zc > 0 && zc < N_HID) {
            if (!s3) {
                int off = __popc(zb & ltm);
                #pragma unroll
                for (int j = 0; j < 16; ++j) off += (j < warp) ? __popc(s_zmask[j]) : 0;
                s_zlist[off] = tid;
            }
            __syncthreads();
        }

        if (tid < N_OUT) {
            float cur4 = 0.f;
            if (zc < N_HID) {
                cur4 = rs4;
                for (int j = 0; j < zc; ++j)
                    cur4 = __fadd_rn(cur4, -g_q4T[s_zlist[j] * N_OUT + tid]);
            }
            float rst4 = (m4 > 1.f) ? 1.f : 0.f;
            m4 = __fadd_rn(__fadd_rn(__fmul_rn(beta4, m4), cur4), -rst4);
            o_s4[(size_t)t * (BATCH * N_OUT)] = (m4 > 1.f) ? 1.f : 0.f;
            o_m4[(size_t)t * (BATCH * N_OUT)] = m4;
        }
        // next step's barrier #1 orders zmask/zlist reads vs. future writes
    }
}

// ---------------------------------------------------------------------------
// Launcher.  Inputs: x, Wch, W1, W2, W3, W4, cochlea_betas, beta1..beta4.
// Output: concat(spk1, spk2, spk3, spk4, mem4), each [T, B, F], float32.
// 5 launches per replay, snn_main at index 3 => ncu capture hits it.
// ---------------------------------------------------------------------------
extern "C" void kernel_launch(void* const* d_in, const int* in_sizes, int n_in,
                              void* d_out, int out_size) {
    const float* x   = (const float*)d_in[0];
    const float* Wch = (const float*)d_in[1];
    const float* W1  = (const float*)d_in[2];
    const float* W2  = (const float*)d_in[3];
    const float* W3  = (const float*)d_in[4];
    const float* W4  = (const float*)d_in[5];
    const float* cb  = (const float*)d_in[6];
    const float* b1  = (const float*)d_in[7];
    const float* b2  = (const float*)d_in[8];
    const float* b3  = (const float*)d_in[9];
    const float* b4  = (const float*)d_in[10];
    float* out = (float*)d_out;

    cudaFuncSetAttribute(cur1_k, cudaFuncAttributeMaxDynamicSharedMemorySize,
                         SW_BYTES);

    prep_quant<<<1024, 256>>>(W1, W2, W3, W4);            // launch 0
    cochlea_rs<<<BATCH, 256>>>(x, Wch, cb);               // launch 1
    cur1_k<<<dim3(BATCH, T_STEPS / CH2, 2), 256, SW_BYTES>>>();  // launch 2
    snn_main<<<BATCH, 512>>>(b1, b2, b3, b4, out);        // launch 3
    pad_b<<<1, 32>>>();                                   // launch 4
}